// round 9
// baseline (speedup 1.0000x reference)
#include <cuda_runtime.h>
#include <math.h>

#define NB 16
#define NPIX 4096
#define NMODE 288

#define INV2DX 5.092958178940651f
#define INVDX2 103.75289746550127f
#define DTC  0.001f
#define NUC  0.002f
#define THETA 0.09817477042468103f

// ---------------- scratch ----------------
static __device__ __align__(16) float  g_h0 [NB*32*NPIX];
static __device__ __align__(16) float  g_h1 [NB*32*NPIX];
static __device__ __align__(16) float2 g_T2 [NMODE*512];    // [mode][bc]
static __device__ __align__(16) float2 g_O  [512*NMODE];    // [bo][mode]
static __device__ __align__(16) float2 g_W  [4*NMODE*1024];
static __device__ __align__(16) float  g_tau[NB*6*NPIX];

__device__ __forceinline__ float4 f4(float a,float b,float c,float d){float4 r;r.x=a;r.y=b;r.z=c;r.w=d;return r;}
__device__ __forceinline__ float4 operator+(float4 a,float4 b){return f4(a.x+b.x,a.y+b.y,a.z+b.z,a.w+b.w);}
__device__ __forceinline__ float4 operator-(float4 a,float4 b){return f4(a.x-b.x,a.y-b.y,a.z-b.z,a.w-b.w);}
__device__ __forceinline__ float4 operator*(float4 a,float s){return f4(a.x*s,a.y*s,a.z*s,a.w*s);}
__device__ __forceinline__ float4 operator*(float4 a,float4 b){return f4(a.x*b.x,a.y*b.y,a.z*b.z,a.w*b.w);}
__device__ __forceinline__ void operator+=(float4&a,float4 b){a.x+=b.x;a.y+=b.y;a.z+=b.z;a.w+=b.w;}

__device__ __forceinline__ float gelu1(float x){
    float t = tanhf(0.7978845608028654f*(x + 0.044715f*x*x*x));
    return 0.5f*x*(1.0f+t);
}

// ---------------- 1) prep ----------------
__global__ void __launch_bounds__(256) prep_kernel(const float* __restrict__ u,
                                                   const float* __restrict__ fc0w,
                                                   const float* __restrict__ fc0b,
                                                   const float2* __restrict__ w1,
                                                   const float2* __restrict__ w2){
    if (blockIdx.x < 256){
        __shared__ float2 sin_[32*145];
        int bid = blockIdx.x;
        int arr = bid >> 7, l = (bid >> 5) & 3, i = bid & 31;
        const float2* src = arr ? w2 : w1;
        for (int t = threadIdx.x; t < 4608; t += 256){
            int o = t / 144, mk = t - o*144;
            sin_[o*145 + mk] = src[((l*32 + i)*32 + o)*144 + mk];
        }
        __syncthreads();
        for (int t = threadIdx.x; t < 4608; t += 256){
            int ml = t >> 5, o = t & 31;
            int mm = ml / 12, ky = ml - mm*12;
            int mode = (arr ? mm + 12 : mm)*12 + ky;
            g_W[((long)(l*NMODE + mode))*1024 + i*32 + o] = sin_[o*145 + ml];
        }
    } else {
        __shared__ float sw[320];
        __shared__ float sb[32];
        for (int i = threadIdx.x; i < 320; i += 256) sw[i] = fc0w[i];
        if (threadIdx.x < 32) sb[threadIdx.x] = fc0b[threadIdx.x];
        __syncthreads();
        int t = (blockIdx.x - 256)*256 + threadIdx.x;
        int b = t >> 12; int pix = t & 4095;
        int x = pix >> 6; int z = pix & 63;
        int xp = (x+1)&63, xm = (x+63)&63;
        float in[10];
        #pragma unroll
        for (int i=0;i<3;i++){
            long base = ((long)(b*3+i))*262144;
            float uc  = u[base + ((x*64+32)<<6) + z];
            float uxp = u[base + ((xp*64+32)<<6) + z];
            float uxm = u[base + ((xm*64+32)<<6) + z];
            float uyp = u[base + ((x*64+33)<<6) + z];
            float uym = u[base + ((x*64+31)<<6) + z];
            in[i*3+0] = (uxp-uxm)*INV2DX;
            in[i*3+1] = (uyp-uym)*INV2DX;
            in[i*3+2] = 0.1f*uc;
        }
        float ssum = 0.f;
        #pragma unroll
        for (int i=0;i<3;i++)
            #pragma unroll
            for (int j=0;j<3;j++){
                float s = 0.5f*(in[i*3+j]+in[j*3+i]);
                ssum += s*s;
            }
        in[9] = sqrtf(2.0f*ssum);
        #pragma unroll
        for (int d=0;d<32;d++){
            float a = sb[d];
            #pragma unroll
            for (int k=0;k<10;k++) a = fmaf(in[k], sw[k*32+d], a);
            g_h0[(b*32+d)*NPIX + pix] = a;
        }
    }
}

// ---------------- 2) forward DFT: z-mirror stage1, kx-paired stage2 ----------------
__global__ void __launch_bounds__(256) fwd_kernel(int flip){
    __shared__ float  tileT[64*65];     // [z][x] padded
    __shared__ float2 c1v[832];         // [x*13+ky]
    __shared__ float2 tw2[64];          // e^{-i theta t}
    __shared__ float2 FCS[64*12];       // [z][ky]
    __shared__ float2 TX[24*64];        // [m][x]

    const float* cur = flip ? g_h1 : g_h0;
    int bc = blockIdx.x;
    int tid = threadIdx.x;
    const float4* src = (const float4*)(cur + (long)bc*NPIX);
    for (int i = tid; i < 1024; i += 256){
        int x = i >> 4, zq4 = i & 15;
        float4 v = src[x*16 + zq4];
        tileT[(zq4*4+0)*65 + x] = v.x;
        tileT[(zq4*4+1)*65 + x] = v.y;
        tileT[(zq4*4+2)*65 + x] = v.z;
        tileT[(zq4*4+3)*65 + x] = v.w;
    }
    if (tid < 64){
        float s,c; sincosf(-THETA*(float)tid, &s, &c);
        tw2[tid] = make_float2(c, s);
    }
    __syncthreads();
    for (int t = tid; t < 768; t += 256){
        int z = t / 12, ky = t - z*12;
        FCS[t] = tw2[(ky*z) & 63];
    }
    for (int t = tid; t < 1536; t += 256){
        int m = t >> 6, x = t & 63;
        int kx = (m < 12) ? m : m + 40;
        TX[t] = tw2[(kx*x) & 63];
    }
    __syncthreads();

    // stage 1: z-DFT with mirror folding; thread = (x, ky-triple)
    {
        int x = tid & 63, kq = tid >> 6;
        int ky0 = kq*3;
        float v0  = tileT[x];
        float v32 = tileT[32*65 + x];
        float r[3], ii[3];
        #pragma unroll
        for (int k = 0; k < 3; k++){
            int ky = ky0 + k;
            float par = (ky & 1) ? -1.0f : 1.0f;
            r[k]  = v0 + v32*par;
            ii[k] = 0.f;
        }
        #pragma unroll 4
        for (int z = 1; z < 32; z++){
            float va = tileT[z*65 + x];
            float vb = tileT[(64-z)*65 + x];
            float vp = va + vb, vm = va - vb;
            #pragma unroll
            for (int k = 0; k < 3; k++){
                float2 w = FCS[z*12 + ky0 + k];
                r[k]  = fmaf(vp, w.x, r[k]);
                ii[k] = fmaf(vm, w.y, ii[k]);
            }
        }
        #pragma unroll
        for (int k = 0; k < 3; k++)
            c1v[x*13 + ky0 + k] = make_float2(r[k], ii[k]);
    }
    __syncthreads();
    // stage 2: 156 tasks (132 conjugate pairs + 24 singles)
    if (tid < 132){
        int mp = 1 + tid/12, ky = tid - (tid/12)*12;
        float A=0,B=0,Cc=0,D=0;
        const float2* tx = &TX[mp*64];
        #pragma unroll 8
        for (int x = 0; x < 64; x++){
            float2 a = c1v[x*13+ky];
            float2 w = tx[x];
            A  = fmaf(a.x, w.x, A);
            B  = fmaf(a.y, w.y, B);
            Cc = fmaf(a.x, w.y, Cc);
            D  = fmaf(a.y, w.x, D);
        }
        g_T2[(mp*12+ky)*512 + bc]      = make_float2(A-B, Cc+D);
        g_T2[((24-mp)*12+ky)*512 + bc] = make_float2(A+B, D-Cc);
    } else if (tid < 156){
        int s = tid - 132;
        int m = (s < 12) ? 0 : 12;
        int ky = s % 12;
        float re=0.f, im=0.f;
        if (m == 0){
            #pragma unroll 8
            for (int x = 0; x < 64; x++){
                float2 a = c1v[x*13+ky];
                re += a.x; im += a.y;
            }
        } else {
            const float2* tx = &TX[12*64];
            #pragma unroll 8
            for (int x = 0; x < 64; x++){
                float2 a = c1v[x*13+ky];
                float2 w = tx[x];
                re += a.x*w.x - a.y*w.y;
                im += a.x*w.y + a.y*w.x;
            }
        }
        g_T2[(m*12+ky)*512 + bc] = make_float2(re, im);
    }
}

// ---------------- 3) per-mode channel mixing: 1152 blocks x 64 thr ----------------
__global__ void __launch_bounds__(64) mode_kernel(int l){
    __shared__ float2 ws[1024];
    __shared__ float2 t2s[128];
    int mode = blockIdx.x >> 2;
    int bq = blockIdx.x & 3;
    const float4* wsrc = (const float4*)(g_W + (long)(l*NMODE + mode)*1024);
    float4* wdst = (float4*)ws;
    #pragma unroll
    for (int j = 0; j < 8; j++) wdst[threadIdx.x + j*64] = wsrc[threadIdx.x + j*64];
    const float4* tsrc = (const float4*)(g_T2 + mode*512 + bq*128);
    ((float4*)t2s)[threadIdx.x] = tsrc[threadIdx.x];
    __syncthreads();
    int b = threadIdx.x >> 4, og = threadIdx.x & 15;
    float r0=0,i0=0,r1=0,i1=0;
    #pragma unroll
    for (int i = 0; i < 32; i++){
        float2 t = t2s[b*32+i];
        float2 wA = ws[i*32+og];
        float2 wB = ws[i*32+og+16];
        r0 = fmaf(t.x,wA.x,fmaf(-t.y,wA.y,r0));
        i0 = fmaf(t.x,wA.y,fmaf( t.y,wA.x,i0));
        r1 = fmaf(t.x,wB.x,fmaf(-t.y,wB.y,r1));
        i1 = fmaf(t.x,wB.y,fmaf( t.y,wB.x,i1));
    }
    int bg = bq*4 + b;
    g_O[(bg*32+og)*NMODE + mode]    = make_float2(r0,i0);
    g_O[(bg*32+og+16)*NMODE + mode] = make_float2(r1,i1);
}

// ---------------- 4) inverse DFT: 2 x-half blocks per (b,o) ----------------
__global__ void __launch_bounds__(256) inv_kernel(int flip){
    __shared__ float2 os[NMODE];
    __shared__ float2 c1v[416];        // [xl*13+ky], scaled
    __shared__ float2 tw2[64];
    __shared__ float2 TXI[24*32];      // [m][xl]
    __shared__ float2 ecs[11*64];      // [ky-1][z] = (2cos, 2sin)
    __shared__ float  sout[32*65];     // [xl][z] padded
    float* nxt = flip ? g_h0 : g_h1;
    int bo = blockIdx.x >> 1;
    int x0 = (blockIdx.x & 1) << 5;
    int tid = threadIdx.x;
    for (int t = tid; t < NMODE; t += 256) os[t] = g_O[bo*NMODE + t];
    if (tid < 64){
        float s,c; sincosf(THETA*(float)tid, &s, &c);
        tw2[tid] = make_float2(c, s);
    }
    __syncthreads();
    for (int t = tid; t < 768; t += 256){
        int m = t >> 5, xl = t & 31;
        int kx = (m < 12) ? m : m + 40;
        TXI[t] = tw2[(kx*(x0+xl)) & 63];
    }
    for (int t = tid; t < 704; t += 256){
        int ky = (t >> 6) + 1, z = t & 63;
        float2 w = tw2[(ky*z) & 63];
        ecs[t] = make_float2(2.0f*w.x, 2.0f*w.y);
    }
    __syncthreads();
    // stage A: 384 outputs (32 xl x 12 ky)
    const float scale = 1.0f/4096.0f;
    #pragma unroll
    for (int p = 0; p < 2; p++){
        int idx = tid + p*256;
        if (idx < 384){
            int xl = idx / 12, ky = idx - xl*12;
            float re = 0.f, im = 0.f;
            #pragma unroll
            for (int m = 0; m < 24; m++){
                float2 a = os[m*12+ky];
                float2 w = TXI[m*32 + xl];
                re += a.x*w.x - a.y*w.y;
                im += a.x*w.y + a.y*w.x;
            }
            c1v[xl*13+ky] = make_float2(re*scale, im*scale);
        }
    }
    __syncthreads();
    // stage B: thread = (xl, zo); 4 mirrored z-pairs each
    {
        int xl = tid & 31, zo = tid >> 5;       // zo 0..7
        int zbase = zo*4;
        float C[4], S[4];
        #pragma unroll
        for (int j = 0; j < 4; j++){ C[j]=0.f; S[j]=0.f; }
        float a0 = c1v[xl*13].x;
        #pragma unroll
        for (int ky = 1; ky < 12; ky++){
            float2 a = c1v[xl*13+ky];
            float ar = a.x, nai = -a.y;
            const float2* e = &ecs[(ky-1)*64 + zbase];
            #pragma unroll
            for (int j = 0; j < 4; j++){
                C[j] = fmaf(ar,  e[j].x, C[j]);
                S[j] = fmaf(nai, e[j].y, S[j]);
            }
        }
        #pragma unroll
        for (int j = 0; j < 4; j++){
            int z = zbase + j;
            sout[xl*65 + z] = a0 + C[j] + S[j];
            if (z > 0) sout[xl*65 + 64 - z] = a0 + C[j] - S[j];
        }
        if (zo == 0){
            float c32 = a0;
            #pragma unroll
            for (int ky = 1; ky < 12; ky++){
                float ar = c1v[xl*13+ky].x;
                c32 = fmaf(ar, ecs[(ky-1)*64 + 32].x, c32);
            }
            sout[xl*65 + 32] = c32;
        }
    }
    __syncthreads();
    for (int p = tid; p < 2048; p += 256){
        int xl = p >> 6, z = p & 63;
        nxt[(long)bo*NPIX + (x0+xl)*64 + z] = sout[xl*65 + z];
    }
}

// ---------------- 5) pointwise conv + add spectral + gelu (thread-per-pixel) ----------------
__global__ void __launch_bounds__(128) conv_gelu_kernel(int flip, const float* __restrict__ cw,
                                                        const float* __restrict__ cb, int apply_gelu){
    __shared__ float ws[1024];
    __shared__ float bs[32];
    const float* cur = flip ? g_h1 : g_h0;
    float* nxt = flip ? g_h0 : g_h1;
    for (int t = threadIdx.x; t < 1024; t += 128) ws[t] = cw[t];
    if (threadIdx.x < 32) bs[threadIdx.x] = cb[threadIdx.x];
    __syncthreads();
    int t = blockIdx.x*128 + threadIdx.x;       // 65536 pixels
    int b = t >> 12, pix = t & 4095;
    const float* base = cur + (long)b*32*NPIX + pix;
    float acc[32];
    #pragma unroll
    for (int o = 0; o < 32; o++) acc[o] = bs[o];
    #pragma unroll 4
    for (int i = 0; i < 32; i++){
        float v = base[(long)i*NPIX];
        #pragma unroll
        for (int o = 0; o < 32; o++)
            acc[o] = fmaf(v, ws[i*32 + o], acc[o]);
    }
    #pragma unroll
    for (int o = 0; o < 32; o++){
        float* sp = nxt + (long)(b*32+o)*NPIX + pix;
        float r = *sp + acc[o];
        if (apply_gelu) r = gelu1(r);
        *sp = r;
    }
}

// ---------------- 6) head (thread-per-pixel) ----------------
__global__ void __launch_bounds__(128) head_kernel(const float* __restrict__ fc1w, const float* __restrict__ fc1b,
                                                   const float* __restrict__ fc2w, const float* __restrict__ fc2b){
    __shared__ float w1s[4096];
    __shared__ float b1s[128];
    __shared__ float w2s[768];
    __shared__ float b2s[6];
    for (int t = threadIdx.x; t < 4096; t += 128) w1s[t] = fc1w[t];
    b1s[threadIdx.x] = fc1b[threadIdx.x];
    for (int t = threadIdx.x; t < 768; t += 128) w2s[t] = fc2w[t];
    if (threadIdx.x < 6) b2s[threadIdx.x] = fc2b[threadIdx.x];
    __syncthreads();
    int t = blockIdx.x*128 + threadIdx.x;       // 65536 pixels
    int b = t >> 12, pix = t & 4095;
    float v[32];
    #pragma unroll
    for (int i = 0; i < 32; i++)
        v[i] = g_h0[(long)(b*32+i)*NPIX + pix];
    float out[6];
    #pragma unroll
    for (int o = 0; o < 6; o++) out[o] = b2s[o];
    #pragma unroll 1
    for (int hc = 0; hc < 16; hc++){
        float hid[8];
        #pragma unroll
        for (int j = 0; j < 8; j++) hid[j] = b1s[hc*8+j];
        #pragma unroll
        for (int i = 0; i < 32; i++){
            #pragma unroll
            for (int j = 0; j < 8; j++)
                hid[j] = fmaf(v[i], w1s[i*128 + hc*8 + j], hid[j]);
        }
        #pragma unroll
        for (int j = 0; j < 8; j++){
            float h = gelu1(hid[j]);
            #pragma unroll
            for (int o = 0; o < 6; o++)
                out[o] = fmaf(h, w2s[(hc*8+j)*6 + o], out[o]);
        }
    }
    #pragma unroll
    for (int o = 0; o < 6; o++)
        g_tau[(long)(b*6+o)*NPIX + pix] = out[o];
}

// ---------------- 7) Navier-Stokes update with fused div(tau) ----------------
__global__ void __launch_bounds__(256) ns_kernel(const float* __restrict__ u, float* __restrict__ out){
    __shared__ float sm[3][16][64];
    int tid = threadIdx.x;
    int col = tid >> 4;
    int z0  = (tid & 15) << 2;
    int bx = blockIdx.x;
    int b = bx >> 8;
    int rem = bx & 255;
    int x = rem >> 2;
    int y = ((rem & 3) << 4) + col;
    int xp=(x+1)&63, xm=(x+63)&63, yp=(y+1)&63, ym=(y+63)&63;

    float4 c[3], vxp[3], vxm[3], vyp[3], vym[3];
    #pragma unroll
    for (int i=0;i<3;i++){
        long bi = (long)(b*3+i)*262144;
        c[i]   = *(const float4*)(u + bi + ((x*64+y)<<6)  + z0);
        *(float4*)&sm[i][col][z0] = c[i];
        vxp[i] = *(const float4*)(u + bi + ((xp*64+y)<<6) + z0);
        vxm[i] = *(const float4*)(u + bi + ((xm*64+y)<<6) + z0);
        vyp[i] = *(const float4*)(u + bi + ((x*64+yp)<<6) + z0);
        vym[i] = *(const float4*)(u + bi + ((x*64+ym)<<6) + z0);
    }

    const float* tb = g_tau + (long)b*6*NPIX;
    #define TT(ch,P,Q) tb[(ch)*NPIX + ((P)<<6) + (Q)]
    float dv0 = (TT(0,xp,y)-TT(0,xm,y) + TT(3,x,yp)-TT(3,x,ym))*INV2DX;
    float dv1 = (TT(3,xp,y)-TT(3,xm,y) + TT(1,x,yp)-TT(1,x,ym))*INV2DX;
    float dv2 = (TT(4,xp,y)-TT(4,xm,y) + TT(5,x,yp)-TT(5,x,ym))*INV2DX;
    #undef TT
    float dv[3] = {dv0, dv1, dv2};

    __syncthreads();

    float4 convd[3];
    convd[0]=f4(0,0,0,0); convd[1]=f4(0,0,0,0); convd[2]=f4(0,0,0,0);
    float4 lap[3];
    #pragma unroll
    for (int i=0;i<3;i++){
        float dn = sm[i][col][(z0+63)&63];
        float up = sm[i][col][(z0+4)&63];
        float4 ci = c[i];
        float4 dz = f4(ci.y-dn, ci.z-ci.x, ci.w-ci.y, up-ci.z) * INV2DX;
        float4 dx = (vxp[i]-vxm[i]) * INV2DX;
        float4 dy = (vyp[i]-vym[i]) * INV2DX;
        float4 zp = f4(ci.y,ci.z,ci.w,up);
        float4 zm = f4(dn,ci.x,ci.y,ci.z);
        float4 lsum = vxp[i]+vxm[i]+vyp[i]+vym[i]+zp+zm - ci*6.0f;
        lap[i] = lsum * INVDX2;
        convd[0] += ci*dx;
        convd[1] += ci*dy;
        convd[2] += ci*dz;
    }
    #pragma unroll
    for (int j=0;j<3;j++){
        float dvj = dv[j];
        long bj = (long)(b*3+j)*262144 + ((x*64+y)<<6) + z0;
        float4 r;
        r.x = c[j].x + DTC*(-convd[j].x + NUC*lap[j].x + dvj);
        r.y = c[j].y + DTC*(-convd[j].y + NUC*lap[j].y + dvj);
        r.z = c[j].z + DTC*(-convd[j].z + NUC*lap[j].z + dvj);
        r.w = c[j].w + DTC*(-convd[j].w + NUC*lap[j].w + dvj);
        *(float4*)(out + bj) = r;
    }
}

// ---------------- launcher ----------------
extern "C" void kernel_launch(void* const* d_in, const int* in_sizes, int n_in,
                              void* d_out, int out_size){
    const float* vel  = (const float*)d_in[0];
    const float* fc0w = (const float*)d_in[1];
    const float* fc0b = (const float*)d_in[2];
    const float* sw1  = (const float*)d_in[3];
    const float* sw2  = (const float*)d_in[4];
    const float* cw   = (const float*)d_in[5];
    const float* cb   = (const float*)d_in[6];
    const float* fc1w = (const float*)d_in[7];
    const float* fc1b = (const float*)d_in[8];
    const float* fc2w = (const float*)d_in[9];
    const float* fc2b = (const float*)d_in[10];
    float* out = (float*)d_out;

    prep_kernel<<<512, 256>>>(vel, fc0w, fc0b, (const float2*)sw1, (const float2*)sw2);
    for (int l = 0; l < 4; l++){
        int flip = l & 1;
        fwd_kernel<<<512, 256>>>(flip);
        mode_kernel<<<1152, 64>>>(l);
        inv_kernel<<<1024, 256>>>(flip);
        conv_gelu_kernel<<<512, 128>>>(flip, cw + l*1024, cb + l*32, (l < 3) ? 1 : 0);
    }
    head_kernel<<<512, 128>>>(fc1w, fc1b, fc2w, fc2b);
    ns_kernel<<<4096, 256>>>(vel, out);
}

// round 10
// speedup vs baseline: 1.0182x; 1.0182x over previous
#include <cuda_runtime.h>
#include <math.h>

#define NB 16
#define NPIX 4096
#define NMODE 288

#define INV2DX 5.092958178940651f
#define INVDX2 103.75289746550127f
#define DTC  0.001f
#define NUC  0.002f
#define THETA 0.09817477042468103f

// ---------------- scratch ----------------
static __device__ __align__(16) float  g_h0 [NB*32*NPIX];
static __device__ __align__(16) float  g_h1 [NB*32*NPIX];
static __device__ __align__(16) float2 g_T2 [NMODE*512];    // [mode][bc]
static __device__ __align__(16) float2 g_O  [512*NMODE];    // [bo][mode]
static __device__ __align__(16) float2 g_W  [4*NMODE*1024];
static __device__ __align__(16) float  g_tau[NB*6*NPIX];

__device__ __forceinline__ float4 f4(float a,float b,float c,float d){float4 r;r.x=a;r.y=b;r.z=c;r.w=d;return r;}
__device__ __forceinline__ float4 operator+(float4 a,float4 b){return f4(a.x+b.x,a.y+b.y,a.z+b.z,a.w+b.w);}
__device__ __forceinline__ float4 operator-(float4 a,float4 b){return f4(a.x-b.x,a.y-b.y,a.z-b.z,a.w-b.w);}
__device__ __forceinline__ float4 operator*(float4 a,float s){return f4(a.x*s,a.y*s,a.z*s,a.w*s);}
__device__ __forceinline__ float4 operator*(float4 a,float4 b){return f4(a.x*b.x,a.y*b.y,a.z*b.z,a.w*b.w);}
__device__ __forceinline__ void operator+=(float4&a,float4 b){a.x+=b.x;a.y+=b.y;a.z+=b.z;a.w+=b.w;}

__device__ __forceinline__ float gelu1(float x){
    float t = tanhf(0.7978845608028654f*(x + 0.044715f*x*x*x));
    return 0.5f*x*(1.0f+t);
}

// ---------------- 1) prep ----------------
__global__ void __launch_bounds__(256) prep_kernel(const float* __restrict__ u,
                                                   const float* __restrict__ fc0w,
                                                   const float* __restrict__ fc0b,
                                                   const float2* __restrict__ w1,
                                                   const float2* __restrict__ w2){
    if (blockIdx.x < 256){
        __shared__ float2 sin_[32*145];
        int bid = blockIdx.x;
        int arr = bid >> 7, l = (bid >> 5) & 3, i = bid & 31;
        const float2* src = arr ? w2 : w1;
        for (int t = threadIdx.x; t < 4608; t += 256){
            int o = t / 144, mk = t - o*144;
            sin_[o*145 + mk] = src[((l*32 + i)*32 + o)*144 + mk];
        }
        __syncthreads();
        for (int t = threadIdx.x; t < 4608; t += 256){
            int ml = t >> 5, o = t & 31;
            int mm = ml / 12, ky = ml - mm*12;
            int mode = (arr ? mm + 12 : mm)*12 + ky;
            g_W[((long)(l*NMODE + mode))*1024 + i*32 + o] = sin_[o*145 + ml];
        }
    } else {
        __shared__ float sw[320];
        __shared__ float sb[32];
        for (int i = threadIdx.x; i < 320; i += 256) sw[i] = fc0w[i];
        if (threadIdx.x < 32) sb[threadIdx.x] = fc0b[threadIdx.x];
        __syncthreads();
        int t = (blockIdx.x - 256)*256 + threadIdx.x;
        int b = t >> 12; int pix = t & 4095;
        int x = pix >> 6; int z = pix & 63;
        int xp = (x+1)&63, xm = (x+63)&63;
        float in[10];
        #pragma unroll
        for (int i=0;i<3;i++){
            long base = ((long)(b*3+i))*262144;
            float uc  = u[base + ((x*64+32)<<6) + z];
            float uxp = u[base + ((xp*64+32)<<6) + z];
            float uxm = u[base + ((xm*64+32)<<6) + z];
            float uyp = u[base + ((x*64+33)<<6) + z];
            float uym = u[base + ((x*64+31)<<6) + z];
            in[i*3+0] = (uxp-uxm)*INV2DX;
            in[i*3+1] = (uyp-uym)*INV2DX;
            in[i*3+2] = 0.1f*uc;
        }
        float ssum = 0.f;
        #pragma unroll
        for (int i=0;i<3;i++)
            #pragma unroll
            for (int j=0;j<3;j++){
                float s = 0.5f*(in[i*3+j]+in[j*3+i]);
                ssum += s*s;
            }
        in[9] = sqrtf(2.0f*ssum);
        #pragma unroll
        for (int d=0;d<32;d++){
            float a = sb[d];
            #pragma unroll
            for (int k=0;k<10;k++) a = fmaf(in[k], sw[k*32+d], a);
            g_h0[(b*32+d)*NPIX + pix] = a;
        }
    }
}

// ---------------- 2) forward DFT: z-mirror stage1, kx-paired stage2 ----------------
__global__ void __launch_bounds__(256) fwd_kernel(int flip){
    __shared__ float  tileT[64*65];
    __shared__ float2 c1v[832];
    __shared__ float2 tw2[64];
    __shared__ float2 FCS[64*12];
    __shared__ float2 TX[24*64];

    const float* cur = flip ? g_h1 : g_h0;
    int bc = blockIdx.x;
    int tid = threadIdx.x;
    const float4* src = (const float4*)(cur + (long)bc*NPIX);
    for (int i = tid; i < 1024; i += 256){
        int x = i >> 4, zq4 = i & 15;
        float4 v = src[x*16 + zq4];
        tileT[(zq4*4+0)*65 + x] = v.x;
        tileT[(zq4*4+1)*65 + x] = v.y;
        tileT[(zq4*4+2)*65 + x] = v.z;
        tileT[(zq4*4+3)*65 + x] = v.w;
    }
    if (tid < 64){
        float s,c; sincosf(-THETA*(float)tid, &s, &c);
        tw2[tid] = make_float2(c, s);
    }
    __syncthreads();
    for (int t = tid; t < 768; t += 256){
        int z = t / 12, ky = t - z*12;
        FCS[t] = tw2[(ky*z) & 63];
    }
    for (int t = tid; t < 1536; t += 256){
        int m = t >> 6, x = t & 63;
        int kx = (m < 12) ? m : m + 40;
        TX[t] = tw2[(kx*x) & 63];
    }
    __syncthreads();

    {
        int x = tid & 63, kq = tid >> 6;
        int ky0 = kq*3;
        float v0  = tileT[x];
        float v32 = tileT[32*65 + x];
        float r[3], ii[3];
        #pragma unroll
        for (int k = 0; k < 3; k++){
            int ky = ky0 + k;
            float par = (ky & 1) ? -1.0f : 1.0f;
            r[k]  = v0 + v32*par;
            ii[k] = 0.f;
        }
        #pragma unroll 4
        for (int z = 1; z < 32; z++){
            float va = tileT[z*65 + x];
            float vb = tileT[(64-z)*65 + x];
            float vp = va + vb, vm = va - vb;
            #pragma unroll
            for (int k = 0; k < 3; k++){
                float2 w = FCS[z*12 + ky0 + k];
                r[k]  = fmaf(vp, w.x, r[k]);
                ii[k] = fmaf(vm, w.y, ii[k]);
            }
        }
        #pragma unroll
        for (int k = 0; k < 3; k++)
            c1v[x*13 + ky0 + k] = make_float2(r[k], ii[k]);
    }
    __syncthreads();
    if (tid < 132){
        int mp = 1 + tid/12, ky = tid - (tid/12)*12;
        float A=0,B=0,Cc=0,D=0;
        const float2* tx = &TX[mp*64];
        #pragma unroll 8
        for (int x = 0; x < 64; x++){
            float2 a = c1v[x*13+ky];
            float2 w = tx[x];
            A  = fmaf(a.x, w.x, A);
            B  = fmaf(a.y, w.y, B);
            Cc = fmaf(a.x, w.y, Cc);
            D  = fmaf(a.y, w.x, D);
        }
        g_T2[(mp*12+ky)*512 + bc]      = make_float2(A-B, Cc+D);
        g_T2[((24-mp)*12+ky)*512 + bc] = make_float2(A+B, D-Cc);
    } else if (tid < 156){
        int s = tid - 132;
        int m = (s < 12) ? 0 : 12;
        int ky = s % 12;
        float re=0.f, im=0.f;
        if (m == 0){
            #pragma unroll 8
            for (int x = 0; x < 64; x++){
                float2 a = c1v[x*13+ky];
                re += a.x; im += a.y;
            }
        } else {
            const float2* tx = &TX[12*64];
            #pragma unroll 8
            for (int x = 0; x < 64; x++){
                float2 a = c1v[x*13+ky];
                float2 w = tx[x];
                re += a.x*w.x - a.y*w.y;
                im += a.x*w.y + a.y*w.x;
            }
        }
        g_T2[(m*12+ky)*512 + bc] = make_float2(re, im);
    }
}

// ---------------- 3) per-mode channel mixing ----------------
__global__ void __launch_bounds__(64) mode_kernel(int l){
    __shared__ float2 ws[1024];
    __shared__ float2 t2s[128];
    int mode = blockIdx.x >> 2;
    int bq = blockIdx.x & 3;
    const float4* wsrc = (const float4*)(g_W + (long)(l*NMODE + mode)*1024);
    float4* wdst = (float4*)ws;
    #pragma unroll
    for (int j = 0; j < 8; j++) wdst[threadIdx.x + j*64] = wsrc[threadIdx.x + j*64];
    const float4* tsrc = (const float4*)(g_T2 + mode*512 + bq*128);
    ((float4*)t2s)[threadIdx.x] = tsrc[threadIdx.x];
    __syncthreads();
    int b = threadIdx.x >> 4, og = threadIdx.x & 15;
    float r0=0,i0=0,r1=0,i1=0;
    #pragma unroll
    for (int i = 0; i < 32; i++){
        float2 t = t2s[b*32+i];
        float2 wA = ws[i*32+og];
        float2 wB = ws[i*32+og+16];
        r0 = fmaf(t.x,wA.x,fmaf(-t.y,wA.y,r0));
        i0 = fmaf(t.x,wA.y,fmaf( t.y,wA.x,i0));
        r1 = fmaf(t.x,wB.x,fmaf(-t.y,wB.y,r1));
        i1 = fmaf(t.x,wB.y,fmaf( t.y,wB.x,i1));
    }
    int bg = bq*4 + b;
    g_O[(bg*32+og)*NMODE + mode]    = make_float2(r0,i0);
    g_O[(bg*32+og+16)*NMODE + mode] = make_float2(r1,i1);
}

// ---------------- 4) inverse DFT: m-paired stage A, x-paired stage B ----------------
__global__ void __launch_bounds__(256) inv_kernel(int flip){
    __shared__ float2 os[NMODE];
    __shared__ float2 c1v[832];        // [x*13+ky], scaled
    __shared__ float2 tw2[64];
    __shared__ float2 TXI[24*64];      // [m][x]
    __shared__ float2 ecs[11*33];      // [ky-1][z<=32] = (2cos, 2sin)
    __shared__ float  sout[64*65];
    float* nxt = flip ? g_h0 : g_h1;
    int bo = blockIdx.x;
    int tid = threadIdx.x;
    for (int t = tid; t < NMODE; t += 256) os[t] = g_O[bo*NMODE + t];
    if (tid < 64){
        float s,c; sincosf(THETA*(float)tid, &s, &c);
        tw2[tid] = make_float2(c, s);
    }
    __syncthreads();
    for (int t = tid; t < 1536; t += 256){
        int m = t >> 6, x = t & 63;
        int kx = (m < 12) ? m : m + 40;
        TXI[t] = tw2[(kx*x) & 63];
    }
    for (int t = tid; t < 363; t += 256){
        int ky = t / 33 + 1, z = t - (t/33)*33;
        float2 w = tw2[(ky*z) & 63];
        ecs[t] = make_float2(2.0f*w.x, 2.0f*w.y);
    }
    __syncthreads();
    // stage A: m-paired (conjugate twiddles); x per lane, ky uniform per warp
    const float scale = 1.0f/4096.0f;
    {
        int x = tid & 63;
        #pragma unroll
        for (int p = 0; p < 3; p++){
            int ky = p*4 + (tid >> 6);
            float2 a0m = os[ky];
            float re = a0m.x, im = a0m.y;
            {
                float2 w12 = TXI[12*64 + x];
                float2 a12 = os[144 + ky];
                re += a12.x*w12.x - a12.y*w12.y;
                im += a12.x*w12.y + a12.y*w12.x;
            }
            #pragma unroll
            for (int m = 1; m < 12; m++){
                float2 wa = TXI[m*64 + x];
                float2 A = os[m*12 + ky];
                float2 B = os[(24-m)*12 + ky];
                re += (A.x + B.x)*wa.x + (B.y - A.y)*wa.y;
                im += (A.y + B.y)*wa.x + (A.x - B.x)*wa.y;
            }
            c1v[x*13+ky] = make_float2(re*scale, im*scale);
        }
    }
    __syncthreads();
    // stage B: thread = (x-pair, zo); 2 x, 4 z, mirrored
    {
        int xp2 = tid & 31, zo = tid >> 5;      // zo 0..7
        int x0 = xp2*2, x1 = x0 + 1;
        int zbase = zo*4;
        float C0[4], S0[4], C1[4], S1[4];
        #pragma unroll
        for (int j = 0; j < 4; j++){ C0[j]=0.f; S0[j]=0.f; C1[j]=0.f; S1[j]=0.f; }
        float a00 = c1v[x0*13].x;
        float a01 = c1v[x1*13].x;
        #pragma unroll
        for (int ky = 1; ky < 12; ky++){
            float2 aa = c1v[x0*13+ky];
            float2 ab = c1v[x1*13+ky];
            const float2* e = &ecs[(ky-1)*33 + zbase];
            #pragma unroll
            for (int j = 0; j < 4; j++){
                float2 ej = e[j];
                C0[j] = fmaf(aa.x,  ej.x, C0[j]);
                S0[j] = fmaf(-aa.y, ej.y, S0[j]);
                C1[j] = fmaf(ab.x,  ej.x, C1[j]);
                S1[j] = fmaf(-ab.y, ej.y, S1[j]);
            }
        }
        #pragma unroll
        for (int j = 0; j < 4; j++){
            int z = zbase + j;
            sout[x0*65 + z] = a00 + C0[j] + S0[j];
            sout[x1*65 + z] = a01 + C1[j] + S1[j];
            if (z > 0){
                sout[x0*65 + 64 - z] = a00 + C0[j] - S0[j];
                sout[x1*65 + 64 - z] = a01 + C1[j] - S1[j];
            }
        }
        if (zo == 0){
            float c320 = a00, c321 = a01;
            #pragma unroll
            for (int ky = 1; ky < 12; ky++){
                float e32 = ecs[(ky-1)*33 + 32].x;
                c320 = fmaf(c1v[x0*13+ky].x, e32, c320);
                c321 = fmaf(c1v[x1*13+ky].x, e32, c321);
            }
            sout[x0*65 + 32] = c320;
            sout[x1*65 + 32] = c321;
        }
    }
    __syncthreads();
    for (int p = tid; p < 4096; p += 256){
        int x = p >> 6, z = p & 63;
        nxt[(long)bo*NPIX + p] = sout[x*65 + z];
    }
}

// ---------------- 5) pointwise conv + add spectral + gelu (pixel-pair) ----------------
__global__ void __launch_bounds__(128) conv_gelu_kernel(int flip, const float* __restrict__ cw,
                                                        const float* __restrict__ cb, int apply_gelu){
    __shared__ float ws[1024];
    __shared__ float bs[32];
    const float* cur = flip ? g_h1 : g_h0;
    float* nxt = flip ? g_h0 : g_h1;
    for (int t = threadIdx.x; t < 1024; t += 128) ws[t] = cw[t];
    if (threadIdx.x < 32) bs[threadIdx.x] = cb[threadIdx.x];
    __syncthreads();
    int t = blockIdx.x*128 + threadIdx.x;
    int b = t >> 11, pp = (t & 2047) << 1;
    const float* base = cur + (long)b*32*NPIX + pp;
    float2 acc[32];
    #pragma unroll
    for (int o = 0; o < 32; o++){ float bb = bs[o]; acc[o] = make_float2(bb, bb); }
    #pragma unroll 4
    for (int i = 0; i < 32; i++){
        float2 v = *(const float2*)(base + (long)i*NPIX);
        #pragma unroll
        for (int o = 0; o < 32; o++){
            float w = ws[i*32 + o];
            acc[o].x = fmaf(v.x, w, acc[o].x);
            acc[o].y = fmaf(v.y, w, acc[o].y);
        }
    }
    #pragma unroll
    for (int o = 0; o < 32; o++){
        float2* sp = (float2*)(nxt + (long)(b*32+o)*NPIX + pp);
        float2 s = *sp;
        float rx = s.x + acc[o].x;
        float ry = s.y + acc[o].y;
        if (apply_gelu){ rx = gelu1(rx); ry = gelu1(ry); }
        *sp = make_float2(rx, ry);
    }
}

// ---------------- 6) head (pixel-pair) ----------------
__global__ void __launch_bounds__(128) head_kernel(const float* __restrict__ fc1w, const float* __restrict__ fc1b,
                                                   const float* __restrict__ fc2w, const float* __restrict__ fc2b){
    __shared__ float w1s[4096];
    __shared__ float b1s[128];
    __shared__ float w2s[768];
    __shared__ float b2s[6];
    for (int t = threadIdx.x; t < 4096; t += 128) w1s[t] = fc1w[t];
    b1s[threadIdx.x] = fc1b[threadIdx.x];
    for (int t = threadIdx.x; t < 768; t += 128) w2s[t] = fc2w[t];
    if (threadIdx.x < 6) b2s[threadIdx.x] = fc2b[threadIdx.x];
    __syncthreads();
    int t = blockIdx.x*128 + threadIdx.x;
    int b = t >> 11, pp = (t & 2047) << 1;
    float2 v[32];
    #pragma unroll
    for (int i = 0; i < 32; i++)
        v[i] = *(const float2*)(g_h0 + (long)(b*32+i)*NPIX + pp);
    float2 out[6];
    #pragma unroll
    for (int o = 0; o < 6; o++){ float bb = b2s[o]; out[o] = make_float2(bb,bb); }
    #pragma unroll 1
    for (int hc = 0; hc < 16; hc++){
        float2 hid[8];
        #pragma unroll
        for (int j = 0; j < 8; j++){ float bb = b1s[hc*8+j]; hid[j] = make_float2(bb,bb); }
        #pragma unroll
        for (int i = 0; i < 32; i++){
            #pragma unroll
            for (int j = 0; j < 8; j++){
                float w = w1s[i*128 + hc*8 + j];
                hid[j].x = fmaf(v[i].x,w,hid[j].x);
                hid[j].y = fmaf(v[i].y,w,hid[j].y);
            }
        }
        #pragma unroll
        for (int j = 0; j < 8; j++){
            float hx = gelu1(hid[j].x), hy = gelu1(hid[j].y);
            #pragma unroll
            for (int o = 0; o < 6; o++){
                float w = w2s[(hc*8+j)*6 + o];
                out[o].x = fmaf(hx,w,out[o].x);
                out[o].y = fmaf(hy,w,out[o].y);
            }
        }
    }
    #pragma unroll
    for (int o = 0; o < 6; o++)
        *(float2*)(g_tau + (long)(b*6+o)*NPIX + pp) = out[o];
}

// ---------------- 7) NS update: fused div(tau), y-neighbors via smem ----------------
__global__ void __launch_bounds__(256) ns_kernel(const float* __restrict__ u, float* __restrict__ out){
    __shared__ float sm[3][16][64];
    int tid = threadIdx.x;
    int col = tid >> 4;
    int z0  = (tid & 15) << 2;
    int bx = blockIdx.x;
    int b = bx >> 8;
    int rem = bx & 255;
    int x = rem >> 2;
    int y = ((rem & 3) << 4) + col;
    int xp=(x+1)&63, xm=(x+63)&63, yp=(y+1)&63, ym=(y+63)&63;

    float4 c[3], vxp[3], vxm[3], vyp[3], vym[3];
    #pragma unroll
    for (int i=0;i<3;i++){
        long bi = (long)(b*3+i)*262144;
        c[i]   = *(const float4*)(u + bi + ((x*64+y)<<6)  + z0);
        *(float4*)&sm[i][col][z0] = c[i];
        vxp[i] = *(const float4*)(u + bi + ((xp*64+y)<<6) + z0);
        vxm[i] = *(const float4*)(u + bi + ((xm*64+y)<<6) + z0);
        if (col == 15) vyp[i] = *(const float4*)(u + bi + ((x*64+yp)<<6) + z0);
        if (col == 0)  vym[i] = *(const float4*)(u + bi + ((x*64+ym)<<6) + z0);
    }

    const float* tb = g_tau + (long)b*6*NPIX;
    #define TT(ch,P,Q) tb[(ch)*NPIX + ((P)<<6) + (Q)]
    float dv0 = (TT(0,xp,y)-TT(0,xm,y) + TT(3,x,yp)-TT(3,x,ym))*INV2DX;
    float dv1 = (TT(3,xp,y)-TT(3,xm,y) + TT(1,x,yp)-TT(1,x,ym))*INV2DX;
    float dv2 = (TT(4,xp,y)-TT(4,xm,y) + TT(5,x,yp)-TT(5,x,ym))*INV2DX;
    #undef TT
    float dv[3] = {dv0, dv1, dv2};

    __syncthreads();

    #pragma unroll
    for (int i=0;i<3;i++){
        if (col < 15) vyp[i] = *(const float4*)&sm[i][col+1][z0];
        if (col > 0)  vym[i] = *(const float4*)&sm[i][col-1][z0];
    }

    float4 convd[3];
    convd[0]=f4(0,0,0,0); convd[1]=f4(0,0,0,0); convd[2]=f4(0,0,0,0);
    float4 lap[3];
    #pragma unroll
    for (int i=0;i<3;i++){
        float dn = sm[i][col][(z0+63)&63];
        float up = sm[i][col][(z0+4)&63];
        float4 ci = c[i];
        float4 dz = f4(ci.y-dn, ci.z-ci.x, ci.w-ci.y, up-ci.z) * INV2DX;
        float4 dx = (vxp[i]-vxm[i]) * INV2DX;
        float4 dy = (vyp[i]-vym[i]) * INV2DX;
        float4 zp = f4(ci.y,ci.z,ci.w,up);
        float4 zm = f4(dn,ci.x,ci.y,ci.z);
        float4 lsum = vxp[i]+vxm[i]+vyp[i]+vym[i]+zp+zm - ci*6.0f;
        lap[i] = lsum * INVDX2;
        convd[0] += ci*dx;
        convd[1] += ci*dy;
        convd[2] += ci*dz;
    }
    #pragma unroll
    for (int j=0;j<3;j++){
        float dvj = dv[j];
        long bj = (long)(b*3+j)*262144 + ((x*64+y)<<6) + z0;
        float4 r;
        r.x = c[j].x + DTC*(-convd[j].x + NUC*lap[j].x + dvj);
        r.y = c[j].y + DTC*(-convd[j].y + NUC*lap[j].y + dvj);
        r.z = c[j].z + DTC*(-convd[j].z + NUC*lap[j].z + dvj);
        r.w = c[j].w + DTC*(-convd[j].w + NUC*lap[j].w + dvj);
        *(float4*)(out + bj) = r;
    }
}

// ---------------- launcher ----------------
extern "C" void kernel_launch(void* const* d_in, const int* in_sizes, int n_in,
                              void* d_out, int out_size){
    const float* vel  = (const float*)d_in[0];
    const float* fc0w = (const float*)d_in[1];
    const float* fc0b = (const float*)d_in[2];
    const float* sw1  = (const float*)d_in[3];
    const float* sw2  = (const float*)d_in[4];
    const float* cw   = (const float*)d_in[5];
    const float* cb   = (const float*)d_in[6];
    const float* fc1w = (const float*)d_in[7];
    const float* fc1b = (const float*)d_in[8];
    const float* fc2w = (const float*)d_in[9];
    const float* fc2b = (const float*)d_in[10];
    float* out = (float*)d_out;

    prep_kernel<<<512, 256>>>(vel, fc0w, fc0b, (const float2*)sw1, (const float2*)sw2);
    for (int l = 0; l < 4; l++){
        int flip = l & 1;
        fwd_kernel<<<512, 256>>>(flip);
        mode_kernel<<<1152, 64>>>(l);
        inv_kernel<<<512, 256>>>(flip);
        conv_gelu_kernel<<<256, 128>>>(flip, cw + l*1024, cb + l*32, (l < 3) ? 1 : 0);
    }
    head_kernel<<<256, 128>>>(fc1w, fc1b, fc2w, fc2b);
    ns_kernel<<<4096, 256>>>(vel, out);
}